// round 2
// baseline (speedup 1.0000x reference)
#include <cuda_runtime.h>
#include <cstdint>

#define N_NODES 50000
#define IN_DIM  256
#define OUT_DIM 256

// Scratch for segment-sum aggregation (device global: allocation-free).
__device__ __align__(16) float g_agg[(size_t)N_NODES * IN_DIM];

// ---------------------------------------------------------------------------
// Kernel 1: zero the aggregation buffer (float4 stores, grid-stride free)
// ---------------------------------------------------------------------------
__global__ void zero_agg_kernel() {
    int i = blockIdx.x * blockDim.x + threadIdx.x;
    const int n4 = (N_NODES * IN_DIM) / 4;
    if (i < n4) {
        float4 z = make_float4(0.f, 0.f, 0.f, 0.f);
        reinterpret_cast<float4*>(g_agg)[i] = z;
    }
}

// ---------------------------------------------------------------------------
// Kernel 2: edge scatter-add. One warp per edge.
// Each lane: 2x LDG.128 of feature[src], 2x red.global.add.v4.f32 to agg[dst].
// ---------------------------------------------------------------------------
__global__ void scatter_add_kernel(const float* __restrict__ feature,
                                   const int*   __restrict__ src,
                                   const int*   __restrict__ dst,
                                   int n_edges) {
    int gwarp = (blockIdx.x * blockDim.x + threadIdx.x) >> 5;
    int lane  = threadIdx.x & 31;
    if (gwarp >= n_edges) return;

    int s = src[gwarp];
    int d = dst[gwarp];

    const float4* f = reinterpret_cast<const float4*>(feature + (size_t)s * IN_DIM);
    float4*       a = reinterpret_cast<float4*>(g_agg + (size_t)d * IN_DIM);

#pragma unroll
    for (int j = 0; j < 2; j++) {
        int idx = lane + 32 * j;           // 64 float4 per row of 256 floats
        float4 v = f[idx];
        asm volatile("red.global.add.v4.f32 [%0], {%1, %2, %3, %4};"
                     :: "l"(a + idx), "f"(v.x), "f"(v.y), "f"(v.z), "f"(v.w)
                     : "memory");
    }
}

// ---------------------------------------------------------------------------
// Kernel 3: SGEMM  out[M,N] = agg[M,K] @ W[K,N],  M=50000, K=256, N=256.
// 64x64 block tile, BK=32, 256 threads, 4x4 per-thread microtile.
// ---------------------------------------------------------------------------
#define BM 64
#define BN 64
#define BK 32

__global__ __launch_bounds__(256) void gemm_kernel(const float* __restrict__ W,
                                                   float* __restrict__ out) {
    __shared__ float As[BK][BM];   // transposed A tile: As[k][m]
    __shared__ float Bs[BK][BN];   // Bs[k][n]

    const int tid = threadIdx.x;          // 0..255
    const int tx = tid & 15;              // 0..15 -> n
    const int ty = tid >> 4;              // 0..15 -> m
    const int m0 = blockIdx.x * BM;
    const int n0 = blockIdx.y * BN;

    float acc[4][4];
#pragma unroll
    for (int i = 0; i < 4; i++)
#pragma unroll
        for (int j = 0; j < 4; j++) acc[i][j] = 0.f;

    for (int k0 = 0; k0 < IN_DIM; k0 += BK) {
        // --- load A tile: 64 rows x 32 cols = 512 float4, 2 per thread ---
#pragma unroll
        for (int l = 0; l < 2; l++) {
            int f4id = tid + 256 * l;      // 0..511
            int row  = f4id >> 3;          // /8  (8 float4 per 32-col row)
            int c4   = f4id & 7;
            float4 v = make_float4(0.f, 0.f, 0.f, 0.f);
            int gm = m0 + row;
            if (gm < N_NODES) {
                v = *reinterpret_cast<const float4*>(
                        g_agg + (size_t)gm * IN_DIM + k0 + c4 * 4);
            }
            As[c4 * 4 + 0][row] = v.x;
            As[c4 * 4 + 1][row] = v.y;
            As[c4 * 4 + 2][row] = v.z;
            As[c4 * 4 + 3][row] = v.w;
        }
        // --- load B tile: 32 rows x 64 cols = 512 float4, 2 per thread ---
#pragma unroll
        for (int l = 0; l < 2; l++) {
            int f4id = tid + 256 * l;      // 0..511
            int row  = f4id >> 4;          // /16 (16 float4 per 64-col row)
            int c4   = f4id & 15;
            float4 v = *reinterpret_cast<const float4*>(
                           W + (size_t)(k0 + row) * OUT_DIM + n0 + c4 * 4);
            *reinterpret_cast<float4*>(&Bs[row][c4 * 4]) = v;
        }
        __syncthreads();

#pragma unroll
        for (int k = 0; k < BK; k++) {
            float4 a4 = reinterpret_cast<float4*>(&As[k][0])[ty];
            float4 b4 = reinterpret_cast<float4*>(&Bs[k][0])[tx];
            float a[4] = {a4.x, a4.y, a4.z, a4.w};
            float b[4] = {b4.x, b4.y, b4.z, b4.w};
#pragma unroll
            for (int i = 0; i < 4; i++)
#pragma unroll
                for (int j = 0; j < 4; j++)
                    acc[i][j] += a[i] * b[j];
        }
        __syncthreads();
    }

    // --- store 4x4 microtile ---
#pragma unroll
    for (int i = 0; i < 4; i++) {
        int gm = m0 + ty * 4 + i;
        if (gm < N_NODES) {
            float4 v = make_float4(acc[i][0], acc[i][1], acc[i][2], acc[i][3]);
            *reinterpret_cast<float4*>(out + (size_t)gm * OUT_DIM + n0 + tx * 4) = v;
        }
    }
}

// ---------------------------------------------------------------------------
extern "C" void kernel_launch(void* const* d_in, const int* in_sizes, int n_in,
                              void* d_out, int out_size) {
    const float* feature = (const float*)d_in[0];
    const float* weight  = (const float*)d_in[1];
    const int*   src     = (const int*)d_in[2];
    const int*   dst     = (const int*)d_in[3];
    float*       out     = (float*)d_out;
    const int n_edges = in_sizes[2];

    // 1) zero agg
    {
        int n4 = (N_NODES * IN_DIM) / 4;
        zero_agg_kernel<<<(n4 + 255) / 256, 256>>>();
    }
    // 2) scatter-add (8 warps / block, one edge per warp)
    {
        int blocks = (n_edges + 7) / 8;
        scatter_add_kernel<<<blocks, 256>>>(feature, src, dst, n_edges);
    }
    // 3) GEMM agg @ W -> out
    {
        dim3 grid((N_NODES + BM - 1) / BM, OUT_DIM / BN);
        gemm_kernel<<<grid, 256>>>(weight, out);
    }
}

// round 3
// speedup vs baseline: 1.0518x; 1.0518x over previous
#include <cuda_runtime.h>
#include <cstdint>

#define N_NODES 50000
#define N_EDGES_MAX 800000
#define IN_DIM  256
#define OUT_DIM 256

// Device-global scratch (allocation-free).
__device__ __align__(16) float g_agg[(size_t)N_NODES * IN_DIM];
__device__ int g_deg[N_NODES];
__device__ int g_off[N_NODES + 1];
__device__ int g_cur[N_NODES];
__device__ int g_esrc[N_EDGES_MAX];

// ---------------------------------------------------------------------------
// Kernel 1: zero degree histogram
// ---------------------------------------------------------------------------
__global__ void zero_deg_kernel() {
    int i = blockIdx.x * blockDim.x + threadIdx.x;
    if (i < N_NODES) g_deg[i] = 0;
}

// ---------------------------------------------------------------------------
// Kernel 2: degree histogram over dst
// ---------------------------------------------------------------------------
__global__ void hist_kernel(const int* __restrict__ dst, int n_edges) {
    int e = blockIdx.x * blockDim.x + threadIdx.x;
    if (e < n_edges) atomicAdd(&g_deg[dst[e]], 1);
}

// ---------------------------------------------------------------------------
// Kernel 3: single-block exclusive scan -> offsets (+ init cursors)
// ---------------------------------------------------------------------------
__global__ void scan_kernel() {
    __shared__ int ssum[1024];
    const int t = threadIdx.x;
    const int chunk = (N_NODES + 1023) / 1024;          // 49
    const int b = t * chunk;
    const int e = min(b + chunk, N_NODES);

    int s = 0;
    for (int i = b; i < e; i++) s += g_deg[i];
    ssum[t] = s;
    __syncthreads();

    // Hillis-Steele inclusive scan over 1024 partials
    for (int d = 1; d < 1024; d <<= 1) {
        int v = (t >= d) ? ssum[t - d] : 0;
        __syncthreads();
        ssum[t] += v;
        __syncthreads();
    }

    int run = ssum[t] - s;                               // exclusive prefix
    for (int i = b; i < e; i++) {
        g_off[i] = run;
        g_cur[i] = run;
        run += g_deg[i];
    }
    if (b < N_NODES && e == N_NODES) g_off[N_NODES] = run;
}

// ---------------------------------------------------------------------------
// Kernel 4: fill CSR edge lists (src ids bucketed by dst)
// ---------------------------------------------------------------------------
__global__ void fill_kernel(const int* __restrict__ src,
                            const int* __restrict__ dst, int n_edges) {
    int e = blockIdx.x * blockDim.x + threadIdx.x;
    if (e < n_edges) {
        int d = dst[e];
        int p = atomicAdd(&g_cur[d], 1);
        g_esrc[p] = src[e];
    }
}

// ---------------------------------------------------------------------------
// Kernel 5: per-node gather-aggregate. One warp per dst node, no atomics.
// ---------------------------------------------------------------------------
__device__ __forceinline__ void acc4(float4& a, float4 v) {
    a.x += v.x; a.y += v.y; a.z += v.z; a.w += v.w;
}

__global__ __launch_bounds__(256) void gather_kernel(const float* __restrict__ feature) {
    int node = (blockIdx.x * blockDim.x + threadIdx.x) >> 5;
    int lane = threadIdx.x & 31;
    if (node >= N_NODES) return;

    int beg = g_off[node];
    int end = g_off[node + 1];

    float4 acc0 = make_float4(0.f, 0.f, 0.f, 0.f);
    float4 acc1 = make_float4(0.f, 0.f, 0.f, 0.f);

    int i = beg;
    for (; i + 2 <= end; i += 2) {
        int s0 = g_esrc[i];
        int s1 = g_esrc[i + 1];
        const float4* f0 = reinterpret_cast<const float4*>(feature + (size_t)s0 * IN_DIM);
        const float4* f1 = reinterpret_cast<const float4*>(feature + (size_t)s1 * IN_DIM);
        float4 v00 = f0[lane];
        float4 v01 = f0[lane + 32];
        float4 v10 = f1[lane];
        float4 v11 = f1[lane + 32];
        acc4(acc0, v00); acc4(acc1, v01);
        acc4(acc0, v10); acc4(acc1, v11);
    }
    if (i < end) {
        int s0 = g_esrc[i];
        const float4* f0 = reinterpret_cast<const float4*>(feature + (size_t)s0 * IN_DIM);
        acc4(acc0, f0[lane]);
        acc4(acc1, f0[lane + 32]);
    }

    float4* a = reinterpret_cast<float4*>(g_agg + (size_t)node * IN_DIM);
    a[lane]      = acc0;
    a[lane + 32] = acc1;
}

// ---------------------------------------------------------------------------
// Kernel 6: SGEMM out = agg @ W via packed f32x2 FFMA (FFMA2).
// 128x128 tile, BK=16, 256 threads, 8x8 microtile (as 8x4 packed pairs).
// ---------------------------------------------------------------------------
#define BM 128
#define BN 128
#define BK 16
#define APAD 4   // As row pad (floats) to cut STS bank conflicts

__device__ __forceinline__ uint64_t packdup(float x) {
    uint64_t r;
    uint32_t u = __float_as_uint(x);
    asm("mov.b64 %0, {%1, %1};" : "=l"(r) : "r"(u));
    return r;
}

__device__ __forceinline__ void ffma2(uint64_t& d, uint64_t a, uint64_t b) {
    asm("fma.rn.f32x2 %0, %1, %2, %0;" : "+l"(d) : "l"(a), "l"(b));
}

__global__ __launch_bounds__(256, 2) void gemm_kernel(const float* __restrict__ W,
                                                      float* __restrict__ out) {
    __shared__ float As[BK][BM + APAD];   // As[k][m]
    __shared__ float Bs[BK][BN];          // Bs[k][n]

    const int tid = threadIdx.x;
    const int tx = tid & 15;              // n: 8 cols  (4 packed pairs)
    const int ty = tid >> 4;              // m: 8 rows
    const int m0 = blockIdx.x * BM;
    const int n0 = blockIdx.y * BN;

    uint64_t acc[8][4];
#pragma unroll
    for (int i = 0; i < 8; i++)
#pragma unroll
        for (int j = 0; j < 4; j++) acc[i][j] = 0ull;

    for (int k0 = 0; k0 < IN_DIM; k0 += BK) {
        // --- A tile: 128 rows x 16 cols = 512 float4, 2 per thread ---
#pragma unroll
        for (int l = 0; l < 2; l++) {
            int f4id = tid + 256 * l;        // 0..511
            int row  = f4id >> 2;            // 4 float4 per 16-col row
            int c4   = f4id & 3;
            float4 v = make_float4(0.f, 0.f, 0.f, 0.f);
            int gm = m0 + row;
            if (gm < N_NODES)
                v = *reinterpret_cast<const float4*>(
                        g_agg + (size_t)gm * IN_DIM + k0 + c4 * 4);
            As[c4 * 4 + 0][row] = v.x;
            As[c4 * 4 + 1][row] = v.y;
            As[c4 * 4 + 2][row] = v.z;
            As[c4 * 4 + 3][row] = v.w;
        }
        // --- B tile: 16 rows x 128 cols = 512 float4, 2 per thread ---
#pragma unroll
        for (int l = 0; l < 2; l++) {
            int f4id = tid + 256 * l;        // 0..511
            int row  = f4id >> 5;            // 32 float4 per 128-col row
            int c4   = f4id & 31;
            *reinterpret_cast<float4*>(&Bs[row][c4 * 4]) =
                *reinterpret_cast<const float4*>(
                    W + (size_t)(k0 + row) * OUT_DIM + n0 + c4 * 4);
        }
        __syncthreads();

#pragma unroll
        for (int k = 0; k < BK; k++) {
            float4 a0 = *reinterpret_cast<const float4*>(&As[k][ty * 8]);
            float4 a1 = *reinterpret_cast<const float4*>(&As[k][ty * 8 + 4]);
            double2 bl = *reinterpret_cast<const double2*>(&Bs[k][tx * 8]);
            double2 bh = *reinterpret_cast<const double2*>(&Bs[k][tx * 8 + 4]);
            uint64_t b2[4];
            b2[0] = (uint64_t)__double_as_longlong(bl.x);
            b2[1] = (uint64_t)__double_as_longlong(bl.y);
            b2[2] = (uint64_t)__double_as_longlong(bh.x);
            b2[3] = (uint64_t)__double_as_longlong(bh.y);
            uint64_t a2[8];
            a2[0] = packdup(a0.x); a2[1] = packdup(a0.y);
            a2[2] = packdup(a0.z); a2[3] = packdup(a0.w);
            a2[4] = packdup(a1.x); a2[5] = packdup(a1.y);
            a2[6] = packdup(a1.z); a2[7] = packdup(a1.w);
#pragma unroll
            for (int i = 0; i < 8; i++)
#pragma unroll
                for (int j = 0; j < 4; j++)
                    ffma2(acc[i][j], a2[i], b2[j]);
        }
        __syncthreads();
    }

    // --- epilogue: 8 rows x 8 cols per thread, 2x16B stores per row ---
#pragma unroll
    for (int i = 0; i < 8; i++) {
        int gm = m0 + ty * 8 + i;
        if (gm < N_NODES) {
            float* orow = out + (size_t)gm * OUT_DIM + n0 + tx * 8;
            ulonglong2 v0, v1;
            v0.x = acc[i][0]; v0.y = acc[i][1];
            v1.x = acc[i][2]; v1.y = acc[i][3];
            *reinterpret_cast<ulonglong2*>(orow)     = v0;
            *reinterpret_cast<ulonglong2*>(orow + 4) = v1;
        }
    }
}

// ---------------------------------------------------------------------------
extern "C" void kernel_launch(void* const* d_in, const int* in_sizes, int n_in,
                              void* d_out, int out_size) {
    const float* feature = (const float*)d_in[0];
    const float* weight  = (const float*)d_in[1];
    const int*   src     = (const int*)d_in[2];
    const int*   dst     = (const int*)d_in[3];
    float*       out     = (float*)d_out;
    const int n_edges = in_sizes[2];

    zero_deg_kernel<<<(N_NODES + 255) / 256, 256>>>();
    hist_kernel<<<(n_edges + 255) / 256, 256>>>(dst, n_edges);
    scan_kernel<<<1, 1024>>>();
    fill_kernel<<<(n_edges + 255) / 256, 256>>>(src, dst, n_edges);
    gather_kernel<<<(N_NODES + 7) / 8, 256>>>(feature);

    dim3 grid((N_NODES + BM - 1) / BM, OUT_DIM / BN);
    gemm_kernel<<<grid, 256>>>(weight, out);
}

// round 6
// speedup vs baseline: 1.4988x; 1.4249x over previous
#include <cuda_runtime.h>
#include <cuda_bf16.h>
#include <cstdint>

#define N_NODES 50000
#define N_EDGES_MAX 800000
#define IN_DIM  256
#define OUT_DIM 256
#define M_PAD   50048          // 391 * 128

// ---------------------------------------------------------------------------
// Device-global scratch (allocation-free).
// ---------------------------------------------------------------------------
__device__ int g_deg[N_NODES];
__device__ int g_off[N_NODES + 1];
__device__ int g_cur[N_NODES];
__device__ int g_esrc[N_EDGES_MAX];
// bf16 split planes of the aggregated features (A) and transposed weight (B)
__device__ __align__(16) __nv_bfloat16 g_hiA[(size_t)M_PAD * IN_DIM];
__device__ __align__(16) __nv_bfloat16 g_loA[(size_t)M_PAD * IN_DIM];
__device__ __align__(16) __nv_bfloat16 g_hiB[(size_t)OUT_DIM * IN_DIM];  // [n][k]
__device__ __align__(16) __nv_bfloat16 g_loB[(size_t)OUT_DIM * IN_DIM];  // [n][k]

// ---------------------------------------------------------------------------
// helpers
// ---------------------------------------------------------------------------
__device__ __forceinline__ uint32_t smem_to_u32(const void* p) {
    uint32_t a;
    asm("{ .reg .u64 t; cvta.to.shared.u64 t, %1; cvt.u32.u64 %0, t; }"
        : "=r"(a) : "l"(p));
    return a;
}
__device__ __forceinline__ void ldm4(uint32_t* r, uint32_t addr) {
    asm volatile("ldmatrix.sync.aligned.m8n8.x4.shared.b16 {%0,%1,%2,%3}, [%4];"
                 : "=r"(r[0]), "=r"(r[1]), "=r"(r[2]), "=r"(r[3]) : "r"(addr));
}
__device__ __forceinline__ void mma16816(float* c, const uint32_t* a,
                                         uint32_t b0, uint32_t b1) {
    asm volatile(
        "mma.sync.aligned.m16n8k16.row.col.f32.bf16.bf16.f32 "
        "{%0,%1,%2,%3}, {%4,%5,%6,%7}, {%8,%9}, {%0,%1,%2,%3};"
        : "+f"(c[0]), "+f"(c[1]), "+f"(c[2]), "+f"(c[3])
        : "r"(a[0]), "r"(a[1]), "r"(a[2]), "r"(a[3]), "r"(b0), "r"(b1));
}

// ---------------------------------------------------------------------------
// Kernel 1: zero degree histogram
// ---------------------------------------------------------------------------
__global__ void zero_deg_kernel() {
    int i = blockIdx.x * blockDim.x + threadIdx.x;
    if (i < N_NODES) g_deg[i] = 0;
}

// ---------------------------------------------------------------------------
// Kernel 2: degree histogram over dst
// ---------------------------------------------------------------------------
__global__ void hist_kernel(const int* __restrict__ dst, int n_edges) {
    int e = blockIdx.x * blockDim.x + threadIdx.x;
    if (e < n_edges) atomicAdd(&g_deg[dst[e]], 1);
}

// ---------------------------------------------------------------------------
// Kernel 3: single-block exclusive scan -> offsets (+ init cursors)
// ---------------------------------------------------------------------------
__global__ void scan_kernel() {
    __shared__ int ssum[1024];
    const int t = threadIdx.x;
    const int chunk = (N_NODES + 1023) / 1024;
    const int b = t * chunk;
    const int e = min(b + chunk, N_NODES);

    int s = 0;
    for (int i = b; i < e; i++) s += g_deg[i];
    ssum[t] = s;
    __syncthreads();
    for (int d = 1; d < 1024; d <<= 1) {
        int v = (t >= d) ? ssum[t - d] : 0;
        __syncthreads();
        ssum[t] += v;
        __syncthreads();
    }
    int run = ssum[t] - s;
    for (int i = b; i < e; i++) {
        g_off[i] = run;
        g_cur[i] = run;
        run += g_deg[i];
    }
    if (b < N_NODES && e == N_NODES) g_off[N_NODES] = run;
}

// ---------------------------------------------------------------------------
// Kernel 4: fill CSR edge lists
// ---------------------------------------------------------------------------
__global__ void fill_kernel(const int* __restrict__ src,
                            const int* __restrict__ dst, int n_edges) {
    int e = blockIdx.x * blockDim.x + threadIdx.x;
    if (e < n_edges) {
        int d = dst[e];
        int p = atomicAdd(&g_cur[d], 1);
        g_esrc[p] = src[e];
    }
}

// ---------------------------------------------------------------------------
// Kernel 5: per-node gather-aggregate -> bf16 hi/lo planes. One warp/node.
// ---------------------------------------------------------------------------
__device__ __forceinline__ void acc4(float4& a, float4 v) {
    a.x += v.x; a.y += v.y; a.z += v.z; a.w += v.w;
}
__device__ __forceinline__ void split4(float4 v, uint2& hi, uint2& lo) {
    __nv_bfloat16 h0 = __float2bfloat16(v.x);
    __nv_bfloat16 h1 = __float2bfloat16(v.y);
    __nv_bfloat16 h2 = __float2bfloat16(v.z);
    __nv_bfloat16 h3 = __float2bfloat16(v.w);
    __nv_bfloat16 l0 = __float2bfloat16(v.x - __bfloat162float(h0));
    __nv_bfloat16 l1 = __float2bfloat16(v.y - __bfloat162float(h1));
    __nv_bfloat16 l2 = __float2bfloat16(v.z - __bfloat162float(h2));
    __nv_bfloat16 l3 = __float2bfloat16(v.w - __bfloat162float(h3));
    __nv_bfloat162 hA = __nv_bfloat162(h0, h1), hB = __nv_bfloat162(h2, h3);
    __nv_bfloat162 lA = __nv_bfloat162(l0, l1), lB = __nv_bfloat162(l2, l3);
    hi.x = *reinterpret_cast<uint32_t*>(&hA); hi.y = *reinterpret_cast<uint32_t*>(&hB);
    lo.x = *reinterpret_cast<uint32_t*>(&lA); lo.y = *reinterpret_cast<uint32_t*>(&lB);
}

__global__ __launch_bounds__(256) void gather_kernel(const float* __restrict__ feature) {
    int node = (blockIdx.x * blockDim.x + threadIdx.x) >> 5;
    int lane = threadIdx.x & 31;
    if (node >= N_NODES) return;

    int beg = g_off[node];
    int end = g_off[node + 1];

    float4 acc0 = make_float4(0.f, 0.f, 0.f, 0.f);
    float4 acc1 = make_float4(0.f, 0.f, 0.f, 0.f);

    int i = beg;
    for (; i + 2 <= end; i += 2) {
        int s0 = g_esrc[i];
        int s1 = g_esrc[i + 1];
        const float4* f0 = reinterpret_cast<const float4*>(feature + (size_t)s0 * IN_DIM);
        const float4* f1 = reinterpret_cast<const float4*>(feature + (size_t)s1 * IN_DIM);
        float4 v00 = f0[lane];
        float4 v01 = f0[lane + 32];
        float4 v10 = f1[lane];
        float4 v11 = f1[lane + 32];
        acc4(acc0, v00); acc4(acc1, v01);
        acc4(acc0, v10); acc4(acc1, v11);
    }
    if (i < end) {
        int s0 = g_esrc[i];
        const float4* f0 = reinterpret_cast<const float4*>(feature + (size_t)s0 * IN_DIM);
        acc4(acc0, f0[lane]);
        acc4(acc1, f0[lane + 32]);
    }

    uint2 h0, l0, h1, l1;
    split4(acc0, h0, l0);
    split4(acc1, h1, l1);
    size_t base = (size_t)node * IN_DIM;
    *reinterpret_cast<uint2*>(g_hiA + base + 4 * lane)       = h0;
    *reinterpret_cast<uint2*>(g_hiA + base + 128 + 4 * lane) = h1;
    *reinterpret_cast<uint2*>(g_loA + base + 4 * lane)       = l0;
    *reinterpret_cast<uint2*>(g_loA + base + 128 + 4 * lane) = l1;
}

// ---------------------------------------------------------------------------
// Kernel 6: convert W -> transposed bf16 hi/lo planes  (B[n][k] = W[k][n])
// ---------------------------------------------------------------------------
__global__ void convw_kernel(const float* __restrict__ W) {
    int idx = blockIdx.x * blockDim.x + threadIdx.x;   // k*256 + n
    if (idx >= IN_DIM * OUT_DIM) return;
    int k = idx >> 8;
    int n = idx & 255;
    float w = W[idx];
    __nv_bfloat16 h = __float2bfloat16(w);
    __nv_bfloat16 l = __float2bfloat16(w - __bfloat162float(h));
    g_hiB[n * IN_DIM + k] = h;
    g_loB[n * IN_DIM + k] = l;
}

// ---------------------------------------------------------------------------
// Kernel 7: bf16 HMMA GEMM (mma.sync m16n8k16), 3 error-compensated passes.
// CTA 128x128 tile, 8 warps (4M x 2N), warp 32x64, K-chunk 64 in smem.
// SW128 XOR swizzle -> conflict-free ldmatrix.
// ---------------------------------------------------------------------------
#define SWX(o) ((o) ^ (((o) >> 3) & 0x70))

__global__ __launch_bounds__(256) void gemm_mma_kernel(float* __restrict__ out) {
    __shared__ __align__(16) uint8_t sA[128 * 128];   // 128 m-rows x 64 bf16
    __shared__ __align__(16) uint8_t sB[128 * 128];   // 128 n-rows x 64 bf16

    const int tid  = threadIdx.x;
    const int lane = tid & 31;
    const int w    = tid >> 5;
    const int warpM = w & 3;          // 0..3
    const int warpN = w >> 2;         // 0..1
    const int m0 = blockIdx.x * 128;
    const int n0 = blockIdx.y * 128;

    const uint32_t sAu = smem_to_u32(sA);
    const uint32_t sBu = smem_to_u32(sB);

    // ldmatrix per-lane address components (row base + xor value)
    // A: lanes 0-15 -> rows (lane&15); lane bit4 -> k half (+16B)
    const int aRow  = warpM * 32 + (lane & 15);
    const uint32_t aXor  = (uint32_t)((aRow << 4) & 0x70);
    const uint32_t aHalf = (uint32_t)((lane >> 4) << 4);         // 0 or 16
    // B: n = (lane&7) + ((lane>>4)<<3); k half = (lane>>3)&1
    const int bRowBase = warpN * 64 + (lane & 7) + (((lane >> 4) & 1) << 3);
    const uint32_t bHalf = (uint32_t)(((lane >> 3) & 1) << 4);   // 0 or 16

    float acc[2][8][4];
#pragma unroll
    for (int mi = 0; mi < 2; mi++)
#pragma unroll
        for (int nf = 0; nf < 8; nf++)
#pragma unroll
            for (int q = 0; q < 4; q++) acc[mi][nf][q] = 0.f;

#pragma unroll 1
    for (int it = 0; it < 12; ++it) {
        const int pass = it >> 2;
        const int k0   = (it & 3) * 64;
        const __nv_bfloat16* Ap = (pass < 2) ? g_hiA : g_loA;
        const __nv_bfloat16* Bp = (pass == 1) ? g_loB : g_hiB;

        // --- load A tile: 128 rows x 128B = 1024 uint4, 4/thread ---
#pragma unroll
        for (int l = 0; l < 4; ++l) {
            int idx = tid + 256 * l;
            int row = idx >> 3;
            int u   = idx & 7;
            uint4 v = *reinterpret_cast<const uint4*>(
                          Ap + (size_t)(m0 + row) * IN_DIM + k0 + u * 8);
            *reinterpret_cast<uint4*>(sA + SWX(row * 128 + u * 16)) = v;
        }
        // --- load B tile ---
#pragma unroll
        for (int l = 0; l < 4; ++l) {
            int idx = tid + 256 * l;
            int row = idx >> 3;
            int u   = idx & 7;
            uint4 v = *reinterpret_cast<const uint4*>(
                          Bp + (size_t)(n0 + row) * IN_DIM + k0 + u * 8);
            *reinterpret_cast<uint4*>(sB + SWX(row * 128 + u * 16)) = v;
        }
        __syncthreads();

#pragma unroll
        for (int ks = 0; ks < 4; ++ks) {
            const uint32_t koff = (uint32_t)(ks * 32);
            // A fragments for mi = 0,1  (rows +0, +16)
            uint32_t afr[2][4];
#pragma unroll
            for (int mi = 0; mi < 2; mi++) {
                uint32_t addr = sAu + (uint32_t)((aRow + mi * 16) * 128)
                              + (((koff + aHalf) ^ ((uint32_t)(((aRow + mi * 16) << 4) & 0x70))));
                ldm4(afr[mi], addr);
            }
#pragma unroll
            for (int nf2 = 0; nf2 < 4; nf2++) {
                const int bRow = bRowBase + nf2 * 16;
                uint32_t baddr = sBu + (uint32_t)(bRow * 128)
                               + ((koff + bHalf) ^ ((uint32_t)((bRow << 4) & 0x70)));
                uint32_t bfr[4];
                ldm4(bfr, baddr);
#pragma unroll
                for (int mi = 0; mi < 2; mi++) {
                    mma16816(acc[mi][nf2 * 2],     afr[mi], bfr[0], bfr[1]);
                    mma16816(acc[mi][nf2 * 2 + 1], afr[mi], bfr[2], bfr[3]);
                }
            }
        }
        __syncthreads();
    }

    // --- epilogue ---
    const int groupID = lane >> 2;
    const int tig     = lane & 3;
#pragma unroll
    for (int mi = 0; mi < 2; mi++) {
#pragma unroll
        for (int nf = 0; nf < 8; nf++) {
            int row0 = m0 + warpM * 32 + mi * 16 + groupID;
            int col  = n0 + warpN * 64 + nf * 8 + tig * 2;
            if (row0 < N_NODES) {
                float2 v0 = make_float2(acc[mi][nf][0], acc[mi][nf][1]);
                *reinterpret_cast<float2*>(out + (size_t)row0 * OUT_DIM + col) = v0;
            }
            int row1 = row0 + 8;
            if (row1 < N_NODES) {
                float2 v1 = make_float2(acc[mi][nf][2], acc[mi][nf][3]);
                *reinterpret_cast<float2*>(out + (size_t)row1 * OUT_DIM + col) = v1;
            }
        }
    }
}

// ---------------------------------------------------------------------------
extern "C" void kernel_launch(void* const* d_in, const int* in_sizes, int n_in,
                              void* d_out, int out_size) {
    const float* feature = (const float*)d_in[0];
    const float* weight  = (const float*)d_in[1];
    const int*   src     = (const int*)d_in[2];
    const int*   dst     = (const int*)d_in[3];
    float*       out     = (float*)d_out;
    const int n_edges = in_sizes[2];

    zero_deg_kernel<<<(N_NODES + 255) / 256, 256>>>();
    hist_kernel<<<(n_edges + 255) / 256, 256>>>(dst, n_edges);
    scan_kernel<<<1, 1024>>>();
    fill_kernel<<<(n_edges + 255) / 256, 256>>>(src, dst, n_edges);
    convw_kernel<<<(IN_DIM * OUT_DIM + 255) / 256, 256>>>(weight);
    gather_kernel<<<(N_NODES + 7) / 8, 256>>>(feature);

    dim3 grid(M_PAD / 128, OUT_DIM / 128);
    gemm_mma_kernel<<<grid, 256>>>(out);
}